// round 7
// baseline (speedup 1.0000x reference)
#include <cuda_runtime.h>
#include <math.h>
#include <stdint.h>

// ---------------- problem constants ----------------
#define N_B     4
#define L_SEQ   256
#define M_MEM   2
#define D_MODEL 768
#define H_HEADS 12
#define FF_DIM  3072
#define LAYERS  4
#define DH      64
#define SEQ     (M_MEM + L_SEQ)      // 258 tokens per batch
#define T_TOT   (N_B * SEQ)          // 1032 total rows (batch-major layout)
#define SLD     264                  // padded leading dim for score rows
#define ZBH     (N_B * H_HEADS)      // 48 (batch, head) pairs

// ---------------- scratch (static device globals; no allocation) ----------------
__device__ float g_x  [T_TOT * D_MODEL];
__device__ float g_q  [T_TOT * D_MODEL];
__device__ float g_k  [T_TOT * D_MODEL];
__device__ float g_v  [T_TOT * D_MODEL];
__device__ float g_ctx[T_TOT * D_MODEL];
__device__ float g_h  [T_TOT * FF_DIM];
__device__ float g_f  [T_TOT * D_MODEL];
__device__ float g_s  [ZBH * SEQ * SLD];

// ---------------- embedding: build x in batch-major order ----------------
// row t = b*SEQ + i ; i<2 -> memory row, else token (i-2)
__global__ void embed_kernel(const int* __restrict__ ids,
                             const float* __restrict__ memory,
                             const float* __restrict__ emb,
                             const float* __restrict__ pos) {
    int idx = blockIdx.x * blockDim.x + threadIdx.x;
    if (idx >= T_TOT * D_MODEL) return;
    int t = idx / D_MODEL, d = idx - t * D_MODEL;
    int b = t / SEQ, i = t - b * SEQ;
    float val;
    if (i < M_MEM) {
        val = memory[(size_t)(b * M_MEM + i) * D_MODEL + d] + pos[(size_t)i * D_MODEL + d];
    } else {
        int l = i - M_MEM;
        int tok = ids[b * L_SEQ + l];
        val = emb[(size_t)tok * D_MODEL + d] + pos[(size_t)(M_MEM + l) * D_MODEL + d];
    }
    g_x[(size_t)t * D_MODEL + d] = val;
}

// ---------------- generic fp32 GEMM: C = act(A @ B + bias) ----------------
// A: Md x Kd row-major (Kd multiple of 16), B: Kd x Nd row-major (Nd multiple of 64)
// grid.z selects one of up to 3 (B, bias, C) sets so QKV runs as one launch.
struct GB { const float* B; const float* bias; float* C; };

__global__ __launch_bounds__(256)
void gemm64(const float* __restrict__ A, GB gb0, GB gb1, GB gb2,
            int Md, int Nd, int Kd, int act) {
    __shared__ __align__(16) float As[16][68];
    __shared__ __align__(16) float Bs[16][68];
    GB gb = (blockIdx.z == 0) ? gb0 : (blockIdx.z == 1 ? gb1 : gb2);
    const float* __restrict__ B = gb.B;

    int tid = threadIdx.x;
    int tx = tid & 15, ty = tid >> 4;
    int row0 = blockIdx.y * 64, col0 = blockIdx.x * 64;
    int ar = tid >> 4, ac = tid & 15;   // A-tile loader coords
    int bc = tid & 63, br = tid >> 6;   // B-tile loader coords

    float acc[4][4] = {};

    for (int k0 = 0; k0 < Kd; k0 += 16) {
#pragma unroll
        for (int p = 0; p < 4; p++) {
            int m = ar + p * 16;
            int gr = row0 + m;
            As[ac][m] = (gr < Md) ? A[(size_t)gr * Kd + k0 + ac] : 0.f;
        }
#pragma unroll
        for (int p = 0; p < 4; p++) {
            int kk = br + p * 4;
            Bs[kk][bc] = B[(size_t)(k0 + kk) * Nd + col0 + bc];
        }
        __syncthreads();
#pragma unroll
        for (int kk = 0; kk < 16; kk++) {
            float4 a4 = *(const float4*)&As[kk][ty * 4];
            float4 b4 = *(const float4*)&Bs[kk][tx * 4];
            float av[4] = {a4.x, a4.y, a4.z, a4.w};
            float bv[4] = {b4.x, b4.y, b4.z, b4.w};
#pragma unroll
            for (int i = 0; i < 4; i++)
#pragma unroll
                for (int j = 0; j < 4; j++)
                    acc[i][j] = fmaf(av[i], bv[j], acc[i][j]);
        }
        __syncthreads();
    }

#pragma unroll
    for (int i = 0; i < 4; i++) {
        int gr = row0 + ty * 4 + i;
        if (gr < Md) {
#pragma unroll
            for (int j = 0; j < 4; j++) {
                int gc = col0 + tx * 4 + j;
                float v = acc[i][j];
                if (gb.bias) v += gb.bias[gc];
                if (act == 1) v = 0.5f * v * (1.f + erff(v * 0.70710678118654752f));
                gb.C[(size_t)gr * Nd + gc] = v;
            }
        }
    }
}

// ---------------- attention scores: S[z] = scale * Q_z @ K_z^T ----------------
// z = b*12 + h ; Q/K rows: x-layout rows b*SEQ.. , head columns h*64..
__global__ __launch_bounds__(256)
void attn_scores(const float* __restrict__ Qb, const float* __restrict__ Kb) {
    __shared__ __align__(16) float As[16][68];
    __shared__ __align__(16) float Bs[16][68];
    int z = blockIdx.z;
    int b = z / H_HEADS, h = z - b * H_HEADS;
    const float* Q  = Qb + (size_t)b * SEQ * D_MODEL + h * DH;
    const float* Km = Kb + (size_t)b * SEQ * D_MODEL + h * DH;
    float* S = g_s + (size_t)z * SEQ * SLD;

    int tid = threadIdx.x;
    int tx = tid & 15, ty = tid >> 4;
    int row0 = blockIdx.y * 64, col0 = blockIdx.x * 64;
    float acc[4][4] = {};

    for (int k0 = 0; k0 < DH; k0 += 16) {
        {
            int ar = tid >> 4, ac = tid & 15;
#pragma unroll
            for (int p = 0; p < 4; p++) {
                int m = ar + p * 16;
                int gr = row0 + m;
                As[ac][m] = (gr < SEQ) ? Q[(size_t)gr * D_MODEL + k0 + ac] : 0.f;
            }
        }
        {   // Bs[d][key] = K[key][d]  (coalesced along d)
            int d = tid & 15, kb = tid >> 4;
#pragma unroll
            for (int p = 0; p < 4; p++) {
                int key = kb + p * 16;
                int gk = col0 + key;
                Bs[d][key] = (gk < SEQ) ? Km[(size_t)gk * D_MODEL + k0 + d] : 0.f;
            }
        }
        __syncthreads();
#pragma unroll
        for (int kk = 0; kk < 16; kk++) {
            float4 a4 = *(const float4*)&As[kk][ty * 4];
            float4 b4 = *(const float4*)&Bs[kk][tx * 4];
            float av[4] = {a4.x, a4.y, a4.z, a4.w};
            float bv[4] = {b4.x, b4.y, b4.z, b4.w};
#pragma unroll
            for (int i = 0; i < 4; i++)
#pragma unroll
                for (int j = 0; j < 4; j++)
                    acc[i][j] = fmaf(av[i], bv[j], acc[i][j]);
        }
        __syncthreads();
    }

    const float scale = 0.125f;  // 1/sqrt(64)
#pragma unroll
    for (int i = 0; i < 4; i++) {
        int gr = row0 + ty * 4 + i;
        if (gr < SEQ) {
#pragma unroll
            for (int j = 0; j < 4; j++) {
                int gc = col0 + tx * 4 + j;
                if (gc < SEQ) S[(size_t)gr * SLD + gc] = acc[i][j] * scale;
            }
        }
    }
}

// ---------------- softmax over 258-wide rows (one warp per row) ----------------
__global__ void softmax_kernel() {
    int gthread = blockIdx.x * blockDim.x + threadIdx.x;
    int warp = gthread >> 5;
    int lane = threadIdx.x & 31;
    if (warp >= ZBH * SEQ) return;
    int z = warp / SEQ, qi = warp - z * SEQ;
    float* row = g_s + (size_t)z * SEQ * SLD + (size_t)qi * SLD;

    float vals[9];
    float mx = -1e30f;
#pragma unroll
    for (int i = 0; i < 9; i++) {
        int j = lane + i * 32;
        vals[i] = (j < SEQ) ? row[j] : -1e30f;
        mx = fmaxf(mx, vals[i]);
    }
#pragma unroll
    for (int o = 16; o; o >>= 1) mx = fmaxf(mx, __shfl_xor_sync(0xffffffffu, mx, o));
    float s = 0.f;
#pragma unroll
    for (int i = 0; i < 9; i++) { vals[i] = expf(vals[i] - mx); s += vals[i]; }
#pragma unroll
    for (int o = 16; o; o >>= 1) s += __shfl_xor_sync(0xffffffffu, s, o);
    float inv = 1.f / s;
#pragma unroll
    for (int i = 0; i < 9; i++) {
        int j = lane + i * 32;
        if (j < SEQ) row[j] = vals[i] * inv;
    }
}

// ---------------- ctx[z] = P[z] @ V_z  (M=SEQ, N=64, K=SEQ) ----------------
__global__ __launch_bounds__(256)
void attn_ctx(const float* __restrict__ Vb, float* __restrict__ Cb) {
    __shared__ __align__(16) float As[16][68];
    __shared__ __align__(16) float Bs[16][68];
    int z = blockIdx.z;
    int b = z / H_HEADS, h = z - b * H_HEADS;
    const float* P = g_s + (size_t)z * SEQ * SLD;
    const float* V = Vb + (size_t)b * SEQ * D_MODEL + h * DH;
    float* C = Cb + (size_t)b * SEQ * D_MODEL + h * DH;

    int tid = threadIdx.x;
    int tx = tid & 15, ty = tid >> 4;
    int row0 = blockIdx.y * 64;
    float acc[4][4] = {};

    for (int k0 = 0; k0 < SEQ; k0 += 16) {
        {
            int ar = tid >> 4, ac = tid & 15;
#pragma unroll
            for (int p = 0; p < 4; p++) {
                int m = ar + p * 16;
                int gr = row0 + m, gk = k0 + ac;
                As[ac][m] = (gr < SEQ && gk < SEQ) ? P[(size_t)gr * SLD + gk] : 0.f;
            }
        }
        {
            int bc = tid & 63, br = tid >> 6;
#pragma unroll
            for (int p = 0; p < 4; p++) {
                int kk = br + p * 4;
                int gk = k0 + kk;
                Bs[kk][bc] = (gk < SEQ) ? V[(size_t)gk * D_MODEL + bc] : 0.f;
            }
        }
        __syncthreads();
#pragma unroll
        for (int kk = 0; kk < 16; kk++) {
            float4 a4 = *(const float4*)&As[kk][ty * 4];
            float4 b4 = *(const float4*)&Bs[kk][tx * 4];
            float av[4] = {a4.x, a4.y, a4.z, a4.w};
            float bv[4] = {b4.x, b4.y, b4.z, b4.w};
#pragma unroll
            for (int i = 0; i < 4; i++)
#pragma unroll
                for (int j = 0; j < 4; j++)
                    acc[i][j] = fmaf(av[i], bv[j], acc[i][j]);
        }
        __syncthreads();
    }

#pragma unroll
    for (int i = 0; i < 4; i++) {
        int gr = row0 + ty * 4 + i;
        if (gr < SEQ) {
#pragma unroll
            for (int j = 0; j < 4; j++) {
                int gc = tx * 4 + j;  // < 64 always
                C[(size_t)gr * D_MODEL + gc] = acc[i][j];
            }
        }
    }
}

// ---------------- fused residual add (+opt bias) + LayerNorm, in-place on x ----------------
__global__ void add_ln_kernel(float* __restrict__ x, const float* __restrict__ add,
                              const float* __restrict__ bias,
                              const float* __restrict__ g, const float* __restrict__ beta) {
    int t = blockIdx.x;
    int tid = threadIdx.x;  // 256 threads, 3 elems each (768)
    float v[3];
    float s = 0.f, ss = 0.f;
#pragma unroll
    for (int i = 0; i < 3; i++) {
        int c = tid + i * 256;
        float val = x[(size_t)t * D_MODEL + c] + add[(size_t)t * D_MODEL + c];
        if (bias) val += bias[c];
        v[i] = val; s += val; ss += val * val;
    }
    __shared__ float rs[8], rss[8];
#pragma unroll
    for (int o = 16; o; o >>= 1) {
        s  += __shfl_xor_sync(0xffffffffu, s, o);
        ss += __shfl_xor_sync(0xffffffffu, ss, o);
    }
    int w = tid >> 5, lane = tid & 31;
    if (lane == 0) { rs[w] = s; rss[w] = ss; }
    __syncthreads();
    float S = 0.f, SS = 0.f;
#pragma unroll
    for (int i = 0; i < 8; i++) { S += rs[i]; SS += rss[i]; }
    float mean = S * (1.f / (float)D_MODEL);
    float var  = SS * (1.f / (float)D_MODEL) - mean * mean;
    float rstd = rsqrtf(var + 1e-5f);
#pragma unroll
    for (int i = 0; i < 3; i++) {
        int c = tid + i * 256;
        x[(size_t)t * D_MODEL + c] = (v[i] - mean) * rstd * g[c] + beta[c];
    }
}

// ---------------- output gather: (N, L, D) = token rows ----------------
__global__ void gather_out(float* __restrict__ out) {
    int idx = blockIdx.x * blockDim.x + threadIdx.x;
    if (idx >= N_B * L_SEQ * D_MODEL) return;
    int d = idx % D_MODEL;
    int r = idx / D_MODEL;           // r = b*L + l
    int b = r / L_SEQ, l = r - b * L_SEQ;
    out[idx] = g_x[(size_t)(b * SEQ + M_MEM + l) * D_MODEL + d];
}

// ---------------- host driver (graph-capturable: kernel launches only) ----------------
extern "C" void kernel_launch(void* const* d_in, const int* in_sizes, int n_in,
                              void* d_out, int out_size) {
    const int*   ids    = (const int*)  d_in[0];
    const float* memory = (const float*)d_in[1];
    const float* emb    = (const float*)d_in[2];
    const float* pos    = (const float*)d_in[3];
    const float* Wq = (const float*)d_in[4];
    const float* bq = (const float*)d_in[5];
    const float* Wk = (const float*)d_in[6];
    const float* bk = (const float*)d_in[7];
    const float* Wv = (const float*)d_in[8];
    const float* bv = (const float*)d_in[9];
    const float* W1 = (const float*)d_in[10];
    const float* b1 = (const float*)d_in[11];
    const float* W2 = (const float*)d_in[12];
    const float* b2 = (const float*)d_in[13];
    const float* g1 = (const float*)d_in[14];
    const float* be1= (const float*)d_in[15];
    const float* g2 = (const float*)d_in[16];
    const float* be2= (const float*)d_in[17];
    float* out = (float*)d_out;

    float *x, *q, *k, *v, *ctx, *h, *f;
    cudaGetSymbolAddress((void**)&x,   g_x);
    cudaGetSymbolAddress((void**)&q,   g_q);
    cudaGetSymbolAddress((void**)&k,   g_k);
    cudaGetSymbolAddress((void**)&v,   g_v);
    cudaGetSymbolAddress((void**)&ctx, g_ctx);
    cudaGetSymbolAddress((void**)&h,   g_h);
    cudaGetSymbolAddress((void**)&f,   g_f);

    embed_kernel<<<(T_TOT * D_MODEL + 255) / 256, 256>>>(ids, memory, emb, pos);

    const int MT = (T_TOT + 63) / 64;  // 17 row tiles

    for (int i = 0; i < LAYERS; i++) {
        const float* Wqi = Wq + (size_t)i * D_MODEL * D_MODEL;
        const float* Wki = Wk + (size_t)i * D_MODEL * D_MODEL;
        const float* Wvi = Wv + (size_t)i * D_MODEL * D_MODEL;
        const float* W1i = W1 + (size_t)i * D_MODEL * FF_DIM;
        const float* W2i = W2 + (size_t)i * FF_DIM * D_MODEL;

        // fused QKV: one launch, grid.z = 3
        GB gq { Wqi, bq + (size_t)i * D_MODEL, q };
        GB gk { Wki, bk + (size_t)i * D_MODEL, k };
        GB gv { Wvi, bv + (size_t)i * D_MODEL, v };
        gemm64<<<dim3(D_MODEL / 64, MT, 3), 256>>>(x, gq, gk, gv,
                                                   T_TOT, D_MODEL, D_MODEL, 0);

        attn_scores<<<dim3(5, 5, ZBH), 256>>>(q, k);
        softmax_kernel<<<(ZBH * SEQ) / 8, 256>>>();   // 12384 rows, 8 warps/block
        attn_ctx<<<dim3(1, 5, ZBH), 256>>>(v, ctx);

        add_ln_kernel<<<T_TOT, 256>>>(x, ctx, nullptr,
                                      g1 + (size_t)i * D_MODEL, be1 + (size_t)i * D_MODEL);

        GB gf1 { W1i, b1 + (size_t)i * FF_DIM, h };
        gemm64<<<dim3(FF_DIM / 64, MT, 1), 256>>>(x, gf1, gf1, gf1,
                                                  T_TOT, FF_DIM, D_MODEL, 1);  // GELU

        GB gf2 { W2i, nullptr, f };
        gemm64<<<dim3(D_MODEL / 64, MT, 1), 256>>>(h, gf2, gf2, gf2,
                                                   T_TOT, D_MODEL, FF_DIM, 0);

        add_ln_kernel<<<T_TOT, 256>>>(x, f, b2 + (size_t)i * D_MODEL,
                                      g2 + (size_t)i * D_MODEL, be2 + (size_t)i * D_MODEL);
    }

    gather_out<<<(N_B * L_SEQ * D_MODEL + 255) / 256, 256>>>(out);
}

// round 9
// speedup vs baseline: 2.2585x; 2.2585x over previous
#include <cuda_runtime.h>
#include <cuda_bf16.h>
#include <math.h>
#include <stdint.h>

// ---------------- problem constants ----------------
#define N_B     4
#define L_SEQ   256
#define M_MEM   2
#define D_MODEL 768
#define H_HEADS 12
#define FF_DIM  3072
#define LAYERS  4
#define DH      64
#define SEQ     (M_MEM + L_SEQ)      // 258 tokens per batch
#define T_TOT   (N_B * SEQ)          // 1032 total rows (batch-major layout)
#define SLD     264                  // padded leading dim for score rows
#define ZBH     (N_B * H_HEADS)      // 48 (batch, head) pairs

// ---------------- PTX helpers (base-target safe: sm_80+ instructions only) ----------------
__device__ __forceinline__ uint32_t smem_u32(const void* p) {
    uint32_t a;
    asm("{ .reg .u64 t; cvta.to.shared.u64 t, %1; cvt.u32.u64 %0, t; }"
        : "=r"(a) : "l"(p));
    return a;
}
__device__ __forceinline__ void ldmatrix_x4(uint32_t* r, uint32_t addr) {
    asm volatile("ldmatrix.sync.aligned.m8n8.x4.shared.b16 {%0,%1,%2,%3}, [%4];"
                 : "=r"(r[0]), "=r"(r[1]), "=r"(r[2]), "=r"(r[3]) : "r"(addr));
}
__device__ __forceinline__ void mma_bf16(float* d, const uint32_t* a, const uint32_t* b) {
    asm volatile(
        "mma.sync.aligned.m16n8k16.row.col.f32.bf16.bf16.f32 "
        "{%0,%1,%2,%3}, {%4,%5,%6,%7}, {%8,%9}, {%0,%1,%2,%3};"
        : "+f"(d[0]), "+f"(d[1]), "+f"(d[2]), "+f"(d[3])
        : "r"(a[0]), "r"(a[1]), "r"(a[2]), "r"(a[3]), "r"(b[0]), "r"(b[1]));
}
__device__ __forceinline__ void cp16(uint32_t dst, const void* src, int bytes) {
    asm volatile("cp.async.ca.shared.global [%0], [%1], 16, %2;"
                 :: "r"(dst), "l"(src), "r"(bytes));
}
#define CP_COMMIT() asm volatile("cp.async.commit_group;" ::: "memory")

// ---------------- scratch (static device globals; no allocation) ----------------
__device__ __align__(16) float g_x  [T_TOT * D_MODEL];
__device__ __align__(16) float g_q  [T_TOT * D_MODEL];
__device__ __align__(16) float g_k  [T_TOT * D_MODEL];
__device__ __align__(16) float g_v  [T_TOT * D_MODEL];
__device__ __align__(16) float g_ctx[T_TOT * D_MODEL];
__device__ __align__(16) float g_f  [T_TOT * D_MODEL];
__device__ __align__(16) float g_s  [ZBH * SEQ * SLD];

// bf16 hi/lo activations
__device__ __align__(16) __nv_bfloat16 g_xh[T_TOT * D_MODEL];
__device__ __align__(16) __nv_bfloat16 g_xl[T_TOT * D_MODEL];
__device__ __align__(16) __nv_bfloat16 g_hh[T_TOT * FF_DIM];
__device__ __align__(16) __nv_bfloat16 g_hl[T_TOT * FF_DIM];

// bf16 hi/lo transposed weights (N-major, K contiguous: [N][K])
__device__ __align__(16) __nv_bfloat16 g_wqT_h[LAYERS * D_MODEL * D_MODEL];
__device__ __align__(16) __nv_bfloat16 g_wqT_l[LAYERS * D_MODEL * D_MODEL];
__device__ __align__(16) __nv_bfloat16 g_wkT_h[LAYERS * D_MODEL * D_MODEL];
__device__ __align__(16) __nv_bfloat16 g_wkT_l[LAYERS * D_MODEL * D_MODEL];
__device__ __align__(16) __nv_bfloat16 g_wvT_h[LAYERS * D_MODEL * D_MODEL];
__device__ __align__(16) __nv_bfloat16 g_wvT_l[LAYERS * D_MODEL * D_MODEL];
__device__ __align__(16) __nv_bfloat16 g_w1T_h[LAYERS * FF_DIM * D_MODEL];
__device__ __align__(16) __nv_bfloat16 g_w1T_l[LAYERS * FF_DIM * D_MODEL];
__device__ __align__(16) __nv_bfloat16 g_w2T_h[LAYERS * D_MODEL * FF_DIM];
__device__ __align__(16) __nv_bfloat16 g_w2T_l[LAYERS * D_MODEL * FF_DIM];

// ---------------- weight transpose + fp32 -> bf16 hi/lo split ----------------
// src: [Kd][Nd] fp32 (layer stride Kd*Nd), dst: [Nd][Kd] bf16 hi/lo
__global__ void convT(const float* __restrict__ src,
                      __nv_bfloat16* __restrict__ dhi,
                      __nv_bfloat16* __restrict__ dlo, int Kd, int Nd) {
    __shared__ __nv_bfloat16 thi[32][33];
    __shared__ __nv_bfloat16 tlo[32][33];
    size_t lo = (size_t)blockIdx.z * Kd * Nd;
    src += lo; dhi += lo; dlo += lo;
    int n0 = blockIdx.x * 32, k0 = blockIdx.y * 32;
    int tx = threadIdx.x, ty = threadIdx.y;
#pragma unroll
    for (int i = ty; i < 32; i += 8) {
        float v = src[(size_t)(k0 + i) * Nd + n0 + tx];
        __nv_bfloat16 h = __float2bfloat16(v);
        thi[i][tx] = h;
        tlo[i][tx] = __float2bfloat16(v - __bfloat162float(h));
    }
    __syncthreads();
#pragma unroll
    for (int i = ty; i < 32; i += 8) {
        dhi[(size_t)(n0 + i) * Kd + k0 + tx] = thi[tx][i];
        dlo[(size_t)(n0 + i) * Kd + k0 + tx] = tlo[tx][i];
    }
}

// ---------------- embedding: build x (fp32 + bf16 hi/lo) ----------------
__global__ void embed_kernel(const int* __restrict__ ids,
                             const float* __restrict__ memory,
                             const float* __restrict__ emb,
                             const float* __restrict__ pos) {
    int idx = blockIdx.x * blockDim.x + threadIdx.x;
    if (idx >= T_TOT * D_MODEL) return;
    int t = idx / D_MODEL, d = idx - t * D_MODEL;
    int b = t / SEQ, i = t - b * SEQ;
    float val;
    if (i < M_MEM) {
        val = memory[(size_t)(b * M_MEM + i) * D_MODEL + d] + pos[(size_t)i * D_MODEL + d];
    } else {
        int l = i - M_MEM;
        int tok = ids[b * L_SEQ + l];
        val = emb[(size_t)tok * D_MODEL + d] + pos[(size_t)(M_MEM + l) * D_MODEL + d];
    }
    g_x[idx] = val;
    __nv_bfloat16 h = __float2bfloat16(val);
    g_xh[idx] = h;
    g_xl[idx] = __float2bfloat16(val - __bfloat162float(h));
}

// ---------------- HMMA GEMM: C = act(A @ Bstored^T + bias) ----------------
// A hi/lo: [Md][Kd] bf16 row-major ; B hi/lo: [Nd][Kd] bf16 row-major
// 3-product split: C = Ah*Bh + Ah*Bl + Al*Bh, fp32 accum.
// CTA tile 128(M) x 64(N), K-chunk 32, 8 warps (4x2), warp tile 32x32.
struct TcB {
    const __nv_bfloat16* Bh; const __nv_bfloat16* Bl;
    const float* bias;
    float* Cf;                             // act 0: fp32 out (+bias)
    __nv_bfloat16* Ch; __nv_bfloat16* Cl;  // act 1: gelu -> bf16 hi/lo out
};

// smem stage layout (rows padded to 80B for conflict-free ldmatrix)
#define ROWB       80
#define OFF_AH     0
#define OFF_AL     10240          // 128*80
#define OFF_BH     20480
#define OFF_BL     25600          // + 64*80
#define STAGE_B    30720
#define GEMM_SMEM  (2 * STAGE_B)  // 61440

__global__ __launch_bounds__(256)
void mma_gemm(const __nv_bfloat16* __restrict__ Ah, const __nv_bfloat16* __restrict__ Al,
              TcB t0, TcB t1, TcB t2, int Md, int Nd, int Kd, int act) {
    extern __shared__ __align__(16) char smem[];
    uint32_t sb = smem_u32(smem);
    TcB tb = (blockIdx.z == 0) ? t0 : (blockIdx.z == 1 ? t1 : t2);

    const int tid = threadIdx.x;
    const int lane = tid & 31, wid = tid >> 5;
    const int wm = wid >> 1, wn = wid & 1;
    const int row0 = blockIdx.y * 128, col0 = blockIdx.x * 64;
    const int nch = Kd >> 5;

    // loader coords
    const int lrow = tid >> 2;      // 0..63
    const int lunit = tid & 3;      // 16B unit within 64B of real data

    float acc[2][4][4] = {};

    // ---- stage loader ----
    auto load_stage = [&](int c) {
        int k0 = c * 32;
        uint32_t s = sb + (c & 1) * STAGE_B;
        // A: 128 rows, 2 per thread (hi+lo)
#pragma unroll
        for (int half = 0; half < 2; half++) {
            int row = lrow + half * 64;
            int gr = row0 + row;
            int by = (gr < Md) ? 16 : 0;
            int grc = (gr < Md) ? gr : 0;
            size_t go = (size_t)grc * Kd + k0 + lunit * 8;
            uint32_t so = row * ROWB + lunit * 16;
            cp16(s + OFF_AH + so, Ah + go, by);
            cp16(s + OFF_AL + so, Al + go, by);
        }
        // B: 64 rows, 1 per thread (hi+lo); N always in-bounds
        {
            int gn = col0 + lrow;
            size_t go = (size_t)gn * Kd + k0 + lunit * 8;
            uint32_t so = lrow * ROWB + lunit * 16;
            cp16(s + OFF_BH + so, tb.Bh + go, 16);
            cp16(s + OFF_BL + so, tb.Bl + go, 16);
        }
        CP_COMMIT();
    };

    load_stage(0);

    for (int c = 0; c < nch; c++) {
        if (c + 1 < nch) {
            load_stage(c + 1);
            asm volatile("cp.async.wait_group 1;" ::: "memory");
        } else {
            asm volatile("cp.async.wait_group 0;" ::: "memory");
        }
        __syncthreads();

        uint32_t s = sb + (c & 1) * STAGE_B;
#pragma unroll
        for (int ks = 0; ks < 2; ks++) {
            uint32_t ah[2][4], al[2][4], bh[2][4], bl[2][4];
#pragma unroll
            for (int mi = 0; mi < 2; mi++) {
                uint32_t ao = s + OFF_AH +
                    (uint32_t)(wm * 32 + mi * 16 + (lane & 15)) * ROWB +
                    ks * 32 + (lane >> 4) * 16;
                ldmatrix_x4(ah[mi], ao);
                ldmatrix_x4(al[mi], ao + (OFF_AL - OFF_AH));
            }
#pragma unroll
            for (int nq = 0; nq < 2; nq++) {
                uint32_t bo = s + OFF_BH +
                    (uint32_t)(wn * 32 + nq * 16 + (lane & 7) + ((lane >> 4) & 1) * 8) * ROWB +
                    ks * 32 + ((lane >> 3) & 1) * 16;
                ldmatrix_x4(bh[nq], bo);
                ldmatrix_x4(bl[nq], bo + (OFF_BL - OFF_BH));
            }
#pragma unroll
            for (int mi = 0; mi < 2; mi++)
#pragma unroll
                for (int ni = 0; ni < 4; ni++) {
                    const uint32_t* ph = &bh[ni >> 1][(ni & 1) * 2];
                    const uint32_t* pl = &bl[ni >> 1][(ni & 1) * 2];
                    mma_bf16(acc[mi][ni], ah[mi], ph);   // Ah*Bh
                    mma_bf16(acc[mi][ni], ah[mi], pl);   // Ah*Bl
                    mma_bf16(acc[mi][ni], al[mi], ph);   // Al*Bh
                }
        }
        __syncthreads();
    }

    // ---- epilogue ----
    const int rbase = row0 + wm * 32 + (lane >> 2);
    const int cbase = col0 + wn * 32 + (lane & 3) * 2;
#pragma unroll
    for (int mi = 0; mi < 2; mi++) {
#pragma unroll
        for (int half = 0; half < 2; half++) {       // d0/d1 vs d2/d3
            int gr = rbase + mi * 16 + half * 8;
            if (gr >= Md) continue;
#pragma unroll
            for (int ni = 0; ni < 4; ni++) {
                int gc = cbase + (ni >> 1) * 16 + (ni & 1) * 8;
                float v0 = acc[mi][ni][half * 2 + 0];
                float v1 = acc[mi][ni][half * 2 + 1];
                if (tb.bias) { v0 += tb.bias[gc]; v1 += tb.bias[gc + 1]; }
                if (act == 0) {
                    float2 o = {v0, v1};
                    *(float2*)(tb.Cf + (size_t)gr * Nd + gc) = o;
                } else {
                    v0 = 0.5f * v0 * (1.f + erff(v0 * 0.70710678118654752f));
                    v1 = 0.5f * v1 * (1.f + erff(v1 * 0.70710678118654752f));
                    __nv_bfloat16 h0 = __float2bfloat16(v0);
                    __nv_bfloat16 h1 = __float2bfloat16(v1);
                    __nv_bfloat162 hp; hp.x = h0; hp.y = h1;
                    __nv_bfloat162 lp;
                    lp.x = __float2bfloat16(v0 - __bfloat162float(h0));
                    lp.y = __float2bfloat16(v1 - __bfloat162float(h1));
                    *(__nv_bfloat162*)(tb.Ch + (size_t)gr * Nd + gc) = hp;
                    *(__nv_bfloat162*)(tb.Cl + (size_t)gr * Nd + gc) = lp;
                }
            }
        }
    }
}

// ---------------- attention scores: S[z] = scale * Q_z @ K_z^T ----------------
__global__ __launch_bounds__(256)
void attn_scores(const float* __restrict__ Qb, const float* __restrict__ Kb) {
    __shared__ __align__(16) float As[16][68];
    __shared__ __align__(16) float Bs[16][68];
    int z = blockIdx.z;
    int b = z / H_HEADS, h = z - b * H_HEADS;
    const float* Q  = Qb + (size_t)b * SEQ * D_MODEL + h * DH;
    const float* Km = Kb + (size_t)b * SEQ * D_MODEL + h * DH;
    float* S = g_s + (size_t)z * SEQ * SLD;

    int tid = threadIdx.x;
    int tx = tid & 15, ty = tid >> 4;
    int row0 = blockIdx.y * 64, col0 = blockIdx.x * 64;
    float acc[4][4] = {};

    for (int k0 = 0; k0 < DH; k0 += 16) {
        {
            int ar = tid >> 4, ac = tid & 15;
#pragma unroll
            for (int p = 0; p < 4; p++) {
                int m = ar + p * 16;
                int gr = row0 + m;
                As[ac][m] = (gr < SEQ) ? Q[(size_t)gr * D_MODEL + k0 + ac] : 0.f;
            }
        }
        {
            int d = tid & 15, kb = tid >> 4;
#pragma unroll
            for (int p = 0; p < 4; p++) {
                int key = kb + p * 16;
                int gk = col0 + key;
                Bs[d][key] = (gk < SEQ) ? Km[(size_t)gk * D_MODEL + k0 + d] : 0.f;
            }
        }
        __syncthreads();
#pragma unroll
        for (int kk = 0; kk < 16; kk++) {
            float4 a4 = *(const float4*)&As[kk][ty * 4];
            float4 b4 = *(const float4*)&Bs[kk][tx * 4];
            float av[4] = {a4.x, a4.y, a4.z, a4.w};
            float bv[4] = {b4.x, b4.y, b4.z, b4.w};
#pragma unroll
            for (int i = 0; i < 4; i++)
#pragma unroll
                for (int j = 0; j < 4; j++)
                    acc[i][j] = fmaf(av[i], bv[j], acc[i][j]);
        }
        __syncthreads();
    }

    const float scale = 0.125f;
#pragma unroll
    for (int i = 0; i < 4; i++) {
        int gr = row0 + ty * 4 + i;
        if (gr < SEQ) {
#pragma unroll
            for (int j = 0; j < 4; j++) {
                int gc = col0 + tx * 4 + j;
                if (gc < SEQ) S[(size_t)gr * SLD + gc] = acc[i][j] * scale;
            }
        }
    }
}

// ---------------- softmax over 258-wide rows (one warp per row) ----------------
__global__ void softmax_kernel() {
    int gthread = blockIdx.x * blockDim.x + threadIdx.x;
    int warp = gthread >> 5;
    int lane = threadIdx.x & 31;
    if (warp >= ZBH * SEQ) return;
    int z = warp / SEQ, qi = warp - z * SEQ;
    float* row = g_s + (size_t)z * SEQ * SLD + (size_t)qi * SLD;

    float vals[9];
    float mx = -1e30f;
#pragma unroll
    for (int i = 0; i < 9; i++) {
        int j = lane + i * 32;
        vals[i] = (j < SEQ) ? row[j] : -1e30f;
        mx = fmaxf(mx, vals[i]);
    }
#pragma unroll
    for (int o = 16; o; o >>= 1) mx = fmaxf(mx, __shfl_xor_sync(0xffffffffu, mx, o));
    float s = 0.f;
#pragma unroll
    for (int i = 0; i < 9; i++) { vals[i] = expf(vals[i] - mx); s += vals[i]; }
#pragma unroll
    for (int o = 16; o; o >>= 1) s += __shfl_xor_sync(0xffffffffu, s, o);
    float inv = 1.f / s;
#pragma unroll
    for (int i = 0; i < 9; i++) {
        int j = lane + i * 32;
        if (j < SEQ) row[j] = vals[i] * inv;
    }
}

// ---------------- ctx[z] = P[z] @ V_z  (M=SEQ, N=64, K=SEQ) ----------------
__global__ __launch_bounds__(256)
void attn_ctx(const float* __restrict__ Vb, float* __restrict__ Cb) {
    __shared__ __align__(16) float As[16][68];
    __shared__ __align__(16) float Bs[16][68];
    int z = blockIdx.z;
    int b = z / H_HEADS, h = z - b * H_HEADS;
    const float* P = g_s + (size_t)z * SEQ * SLD;
    const float* V = Vb + (size_t)b * SEQ * D_MODEL + h * DH;
    float* C = Cb + (size_t)b * SEQ * D_MODEL + h * DH;

    int tid = threadIdx.x;
    int tx = tid & 15, ty = tid >> 4;
    int row0 = blockIdx.y * 64;
    float acc[4][4] = {};

    for (int k0 = 0; k0 < SEQ; k0 += 16) {
        {
            int ar = tid >> 4, ac = tid & 15;
#pragma unroll
            for (int p = 0; p < 4; p++) {
                int m = ar + p * 16;
                int gr = row0 + m, gk = k0 + ac;
                As[ac][m] = (gr < SEQ && gk < SEQ) ? P[(size_t)gr * SLD + gk] : 0.f;
            }
        }
        {
            int bc = tid & 63, br = tid >> 6;
#pragma unroll
            for (int p = 0; p < 4; p++) {
                int kk = br + p * 4;
                int gk = k0 + kk;
                Bs[kk][bc] = (gk < SEQ) ? V[(size_t)gk * D_MODEL + bc] : 0.f;
            }
        }
        __syncthreads();
#pragma unroll
        for (int kk = 0; kk < 16; kk++) {
            float4 a4 = *(const float4*)&As[kk][ty * 4];
            float4 b4 = *(const float4*)&Bs[kk][tx * 4];
            float av[4] = {a4.x, a4.y, a4.z, a4.w};
            float bv[4] = {b4.x, b4.y, b4.z, b4.w};
#pragma unroll
            for (int i = 0; i < 4; i++)
#pragma unroll
                for (int j = 0; j < 4; j++)
                    acc[i][j] = fmaf(av[i], bv[j], acc[i][j]);
        }
        __syncthreads();
    }

#pragma unroll
    for (int i = 0; i < 4; i++) {
        int gr = row0 + ty * 4 + i;
        if (gr < SEQ) {
#pragma unroll
            for (int j = 0; j < 4; j++) {
                int gc = tx * 4 + j;
                C[(size_t)gr * D_MODEL + gc] = acc[i][j];
            }
        }
    }
}

// ---------------- fused residual add (+opt bias) + LayerNorm -> x + bf16 hi/lo ----------------
__global__ void add_ln_kernel(float* __restrict__ x, const float* __restrict__ add,
                              const float* __restrict__ bias,
                              const float* __restrict__ g, const float* __restrict__ beta) {
    int t = blockIdx.x;
    int tid = threadIdx.x;
    float v[3];
    float s = 0.f, ss = 0.f;
#pragma unroll
    for (int i = 0; i < 3; i++) {
        int c = tid + i * 256;
        float val = x[(size_t)t * D_MODEL + c] + add[(size_t)t * D_MODEL + c];
        if (bias) val += bias[c];
        v[i] = val; s += val; ss += val * val;
    }
    __shared__ float rs[8], rss[8];
#pragma unroll
    for (int o = 16; o; o >>= 1) {
        s  += __shfl_xor_sync(0xffffffffu, s, o);
        ss += __shfl_xor_sync(0xffffffffu, ss, o);
    }
    int w = tid >> 5, lane = tid & 31;
    if (lane == 0) { rs[w] = s; rss[w] = ss; }
    __syncthreads();
    float S = 0.f, SS = 0.f;
#pragma unroll
    for (int i = 0; i < 8; i++) { S += rs[i]; SS += rss[i]; }
    float mean = S * (1.f / (float)D_MODEL);
    float var  = SS * (1.f / (float)D_MODEL) - mean * mean;
    float rstd = rsqrtf(var + 1e-5f);
#pragma unroll
    for (int i = 0; i < 3; i++) {
        int c = tid + i * 256;
        float o = (v[i] - mean) * rstd * g[c] + beta[c];
        size_t idx = (size_t)t * D_MODEL + c;
        x[idx] = o;
        __nv_bfloat16 h = __float2bfloat16(o);
        g_xh[idx] = h;
        g_xl[idx] = __float2bfloat16(o - __bfloat162float(h));
    }
}

// ---------------- output gather ----------------
__global__ void gather_out(float* __restrict__ out) {
    int idx = blockIdx.x * blockDim.x + threadIdx.x;
    if (idx >= N_B * L_SEQ * D_MODEL) return;
    int d = idx % D_MODEL;
    int r = idx / D_MODEL;
    int b = r / L_SEQ, l = r - b * L_SEQ;
    out[idx] = g_x[(size_t)(b * SEQ + M_MEM + l) * D_MODEL + d];
}

// ---------------- host driver ----------------
extern "C" void kernel_launch(void* const* d_in, const int* in_sizes, int n_in,
                              void* d_out, int out_size) {
    const int*   ids    = (const int*)  d_in[0];
    const float* memory = (const float*)d_in[1];
    const float* emb    = (const float*)d_in[2];
    const float* pos    = (const float*)d_in[3];
    const float* Wq = (const float*)d_in[4];
    const float* bq = (const float*)d_in[5];
    const float* Wk = (const float*)d_in[6];
    const float* bk = (const float*)d_in[7];
    const float* Wv = (const float*)d_in[8];
    const float* bv = (const float*)d_in[9];
    const float* W1 = (const float*)d_in[10];
    const float* b1 = (const float*)d_in[11];
    const float* W2 = (const float*)d_in[12];
    const float* b2 = (const float*)d_in[13];
    const float* g1 = (const float*)d_in[14];
    const float* be1= (const float*)d_in[15];
    const float* g2 = (const float*)d_in[16];
    const float* be2= (const float*)d_in[17];
    float* out = (float*)d_out;

    float *x, *q, *k, *v, *ctx, *f;
    __nv_bfloat16 *xh, *xl, *hh, *hl;
    __nv_bfloat16 *wqh, *wql, *wkh, *wkl, *wvh, *wvl, *w1h, *w1l, *w2h, *w2l;
    cudaGetSymbolAddress((void**)&x,   g_x);
    cudaGetSymbolAddress((void**)&q,   g_q);
    cudaGetSymbolAddress((void**)&k,   g_k);
    cudaGetSymbolAddress((void**)&v,   g_v);
    cudaGetSymbolAddress((void**)&ctx, g_ctx);
    cudaGetSymbolAddress((void**)&f,   g_f);
    cudaGetSymbolAddress((void**)&xh,  g_xh);
    cudaGetSymbolAddress((void**)&xl,  g_xl);
    cudaGetSymbolAddress((void**)&hh,  g_hh);
    cudaGetSymbolAddress((void**)&hl,  g_hl);
    cudaGetSymbolAddress((void**)&wqh, g_wqT_h);
    cudaGetSymbolAddress((void**)&wql, g_wqT_l);
    cudaGetSymbolAddress((void**)&wkh, g_wkT_h);
    cudaGetSymbolAddress((void**)&wkl, g_wkT_l);
    cudaGetSymbolAddress((void**)&wvh, g_wvT_h);
    cudaGetSymbolAddress((void**)&wvl, g_wvT_l);
    cudaGetSymbolAddress((void**)&w1h, g_w1T_h);
    cudaGetSymbolAddress((void**)&w1l, g_w1T_l);
    cudaGetSymbolAddress((void**)&w2h, g_w2T_h);
    cudaGetSymbolAddress((void**)&w2l, g_w2T_l);

    cudaFuncSetAttribute(mma_gemm, cudaFuncAttributeMaxDynamicSharedMemorySize, GEMM_SMEM);

    // weight conversion (transpose + bf16 hi/lo split)
    dim3 ctb(32, 8);
    convT<<<dim3(D_MODEL / 32, D_MODEL / 32, LAYERS), ctb>>>(Wq, wqh, wql, D_MODEL, D_MODEL);
    convT<<<dim3(D_MODEL / 32, D_MODEL / 32, LAYERS), ctb>>>(Wk, wkh, wkl, D_MODEL, D_MODEL);
    convT<<<dim3(D_MODEL / 32, D_MODEL / 32, LAYERS), ctb>>>(Wv, wvh, wvl, D_MODEL, D_MODEL);
    convT<<<dim3(FF_DIM / 32, D_MODEL / 32, LAYERS), ctb>>>(W1, w1h, w1l, D_MODEL, FF_DIM);
    convT<<<dim3(D_MODEL / 32, FF_DIM / 32, LAYERS), ctb>>>(W2, w2h, w2l, FF_DIM, D_MODEL);

    embed_kernel<<<(T_TOT * D_MODEL + 255) / 256, 256>>>(ids, memory, emb, pos);

    const int MT = (T_TOT + 127) / 128;  // 9 row tiles

    for (int i = 0; i < LAYERS; i++) {
        size_t od = (size_t)i * D_MODEL * D_MODEL;
        size_t of = (size_t)i * D_MODEL * FF_DIM;

        TcB tq { wqh + od, wql + od, bq + (size_t)i * D_MODEL, q, nullptr, nullptr };
        TcB tk { wkh + od, wkl + od, bk + (size_t)i * D_MODEL, k, nullptr, nullptr };
        TcB tv { wvh + od, wvl + od, bv + (size_t)i * D_MODEL, v, nullptr, nullptr };
        mma_gemm<<<dim3(D_MODEL / 64, MT, 3), 256, GEMM_SMEM>>>(
            xh, xl, tq, tk, tv, T_TOT, D_MODEL, D_MODEL, 0);

        attn_scores<<<dim3(5, 5, ZBH), 256>>>(q, k);
        softmax_kernel<<<(ZBH * SEQ) / 8, 256>>>();
        attn_ctx<<<dim3(1, 5, ZBH), 256>>>(v, ctx);

        add_ln_kernel<<<T_TOT, 256>>>(x, ctx, nullptr,
                                      g1 + (size_t)i * D_MODEL, be1 + (size_t)i * D_MODEL);

        TcB t1 { w1h + of, w1l + of, b1 + (size_t)i * FF_DIM, nullptr, hh, hl };
        mma_gemm<<<dim3(FF_DIM / 64, MT, 1), 256, GEMM_SMEM>>>(
            xh, xl, t1, t1, t1, T_TOT, FF_DIM, D_MODEL, 1);

        TcB t2 { w2h + of, w2l + of, nullptr, f, nullptr, nullptr };
        mma_gemm<<<dim3(D_MODEL / 64, MT, 1), 256, GEMM_SMEM>>>(
            hh, hl, t2, t2, t2, T_TOT, D_MODEL, FF_DIM, 0);

        add_ln_kernel<<<T_TOT, 256>>>(x, f, b2 + (size_t)i * D_MODEL,
                                      g2 + (size_t)i * D_MODEL, be2 + (size_t)i * D_MODEL);
    }

    gather_out<<<(N_B * L_SEQ * D_MODEL + 255) / 256, 256>>>(out);
}